// round 17
// baseline (speedup 1.0000x reference)
#include <cuda_runtime.h>
#include <cuda_fp16.h>
#include <math.h>
#include <stdint.h>

#define BATCH 4
#define HW    512
#define CMID  64

// ---------------------------------------------------------------------------
// Scratch (allocation-free rule: __device__ globals)
// ---------------------------------------------------------------------------
__device__ __align__(256) __half g_h1o[(size_t)BATCH * HW * HW * CMID];   // conv1 offsets out
__device__ __align__(256) __half g_h1w[(size_t)BATCH * HW * HW * CMID];   // conv1 weights out
__device__ __align__(256) __half g_h2o[(size_t)BATCH * HW * HW * CMID];   // conv2 offsets out
__device__ __align__(256) __half g_h2w[(size_t)BATCH * HW * HW * CMID];   // conv2 weights out
__device__ __align__(256) __half g_wp1o[9 * 64 * 32];
__device__ __align__(256) __half g_wp1w[9 * 64 * 32];
__device__ __align__(256) __half g_wp2o[9 * 64 * 64];
__device__ __align__(256) __half g_wp2w[9 * 64 * 64];
__device__ int g_cls[BATCH];

__device__ __forceinline__ uint32_t smem_u32(const void* p) {
    uint32_t a;
    asm("{ .reg .u64 t; cvta.to.shared.u64 t, %1; cvt.u32.u64 %0, t; }"
        : "=r"(a) : "l"(p));
    return a;
}
__device__ __forceinline__ void ldm_x4(uint32_t* r, uint32_t addr) {
    asm volatile("ldmatrix.sync.aligned.m8n8.x4.shared.b16 {%0,%1,%2,%3}, [%4];"
                 : "=r"(r[0]), "=r"(r[1]), "=r"(r[2]), "=r"(r[3]) : "r"(addr));
}
__device__ __forceinline__ void mma16816(float* d, const uint32_t* a, const uint32_t* b) {
    asm volatile(
        "mma.sync.aligned.m16n8k16.row.col.f32.f16.f16.f32 "
        "{%0,%1,%2,%3}, {%4,%5,%6,%7}, {%8,%9}, {%0,%1,%2,%3};"
        : "+f"(d[0]), "+f"(d[1]), "+f"(d[2]), "+f"(d[3])
        : "r"(a[0]), "r"(a[1]), "r"(a[2]), "r"(a[3]), "r"(b[0]), "r"(b[1]));
}
// 16B async copy; src_sz = 16 (copy) or 0 (zero-fill 16B)
__device__ __forceinline__ void cp16(uint32_t dst, const void* src, int src_sz) {
    asm volatile("cp.async.ca.shared.global [%0], [%1], 16, %2;"
                 :: "r"(dst), "l"(src), "r"(src_sz) : "memory");
}
__device__ __forceinline__ void cp_commit() {
    asm volatile("cp.async.commit_group;" ::: "memory");
}
__device__ __forceinline__ void cp_wait_all() {
    asm volatile("cp.async.wait_group 0;" ::: "memory");
}

// ---------------------------------------------------------------------------
// Weight prep (all 4 tensors in ONE launch; blockIdx.y selects tensor):
// HWIO fp32 w[(tap*CIN+ci)*64+co] -> wp[(tap*64 + co)*CIN + ci]
// ---------------------------------------------------------------------------
__global__ void prep_all(const float* __restrict__ Wo1, const float* __restrict__ Ww1,
                         const float* __restrict__ Wo2, const float* __restrict__ Ww2,
                         __half* __restrict__ p1o, __half* __restrict__ p1w,
                         __half* __restrict__ p2o, __half* __restrict__ p2w)
{
    const int sel = blockIdx.y;
    const float* w  = sel == 0 ? Wo1 : sel == 1 ? Ww1 : sel == 2 ? Wo2 : Ww2;
    __half*      wp = sel == 0 ? p1o : sel == 1 ? p1w : sel == 2 ? p2o : p2w;
    const int CIN = (sel < 2) ? 32 : 64;

    int total = 9 * CIN * 64;
    for (int i = blockIdx.x * 256 + threadIdx.x; i < total; i += gridDim.x * 256) {
        int co  = i % 64;
        int ci  = (i / 64) % CIN;
        int tap = i / (64 * CIN);
        wp[((size_t)tap * 64 + co) * CIN + ci] = __float2half_rn(w[i]);
    }
}

// ---------------------------------------------------------------------------
// conv1 FUSED: both branches in one block. 32 -> 2x64 co, ReLU, fp16 out.
// GEMM M=128 (4 rows x 32 px), N=128 (branch o | branch w).
// 8 warps = 4(M) x 2(N-branch); warp tile 32(M) x 64(N). PERSISTENT:
// block loops 8 y-tiles; ALL 9 B taps of BOTH branches staged once.
// A staged ONCE per tile and shared by both branches (this is the win).
// Epilogue: per-branch pass through Os (aliases dead A region) -> STG.128.
// ---------------------------------------------------------------------------
__global__ void __launch_bounds__(256, 2)
conv1_fused(const float* __restrict__ in,
            const __half* __restrict__ wp0, const __half* __restrict__ wp1,
            const float* __restrict__ bias0, const float* __restrict__ bias1,
            __half* __restrict__ out0, __half* __restrict__ out1)
{
    constexpr int CIN    = 32;
    constexpr int APITCH = CIN * 2 + 16;     // 80
    constexpr int BPITCH = CIN * 2 + 16;     // 80
    constexpr int NPX    = 6 * 34;           // 204 staged pixels
    constexpr int BHALF  = 9 * 64 * BPITCH;  // 46080 per branch
    constexpr int OPITCH = 144;

    extern __shared__ char sm[];
    float* bias_s = (float*)sm;                      // 512 B (128 floats)
    char*  As = sm + 512;                            // max(204*80, 128*144)=18432
    char*  Os = As;                                  // aliases A after MMAs
    char*  Bs = As + 18432;                          // 2 * 46080

    const int tid  = threadIdx.x;
    const int lane = tid & 31;
    const int wid  = tid >> 5;
    const int wm   = wid >> 1;        // M row 0..3
    const int wn   = wid & 1;         // branch 0=offsets, 1=weights
    const int x0   = blockIdx.x * 32;
    const int batch = blockIdx.z;

    const float* ib = in + (size_t)batch * HW * HW * CIN;

    if (tid < 64) bias_s[tid] = bias0[tid];
    else if (tid < 128) bias_s[tid] = bias1[tid - 64];

    const uint32_t AsU = smem_u32(As);
    const uint32_t BsU = smem_u32(Bs);

    // --- stage ALL 9 B taps of BOTH branches once per block
    {
        constexpr int CH = CIN / 8;   // 4
        for (int i = tid; i < 2 * 9 * 64 * CH; i += 256) {
            int c   = i % CH;
            int row = (i / CH) & 63;
            int tap = (i / (CH * 64)) % 9;
            int br  = i / (CH * 64 * 9);
            const __half* wp = br ? wp1 : wp0;
            cp16(BsU + br * BHALF + (tap * 64 + row) * BPITCH + c * 16,
                 wp + ((size_t)tap * 64 + row) * CIN + c * 8, 16);
        }
        cp_commit();
        cp_wait_all();
    }

    const int brow_in = (lane & 7) + ((lane >> 4) & 1) * 8;
    const int bcol    = ((lane >> 3) & 1) * 16;
    const int acol    = (lane >> 4) * 16;
    const int apx     = (lane & 15);
    const uint32_t Bbr = BsU + wn * BHALF;

    for (int it = 0; it < 8; ++it) {
        const int y0 = blockIdx.y * 32 + it * 4;

        __syncthreads();   // WAR: prior iter's Os reads done before A rewrite

        // --- stage A: 6 rows (y0-1 .. y0+4) x 34 px, fp32 -> fp16
        for (int i = tid; i < NPX * (CIN / 4); i += 256) {
            int ci4 = i & 7;
            int px  = i >> 3;
            int irow = px / 34, c = px % 34;
            int gy = y0 - 1 + irow;
            int gx = x0 - 1 + c;
            float4 v = make_float4(0.f, 0.f, 0.f, 0.f);
            if ((unsigned)gy < HW && (unsigned)gx < HW)
                v = *(const float4*)&ib[((size_t)gy * HW + gx) * CIN + ci4 * 4];
            __half2 h0 = __float22half2_rn(make_float2(v.x, v.y));
            __half2 h1 = __float22half2_rn(make_float2(v.z, v.w));
            *(uint2*)(As + px * APITCH + ci4 * 8) =
                make_uint2(*(uint32_t*)&h0, *(uint32_t*)&h1);
        }
        __syncthreads();   // A ready

        float acc[2][8][4];
#pragma unroll
        for (int mf = 0; mf < 2; ++mf)
#pragma unroll
            for (int nf = 0; nf < 8; ++nf)
#pragma unroll
                for (int q = 0; q < 4; ++q) acc[mf][nf][q] = 0.f;

        for (int ky = 0; ky < 3; ++ky) {
#pragma unroll
            for (int kx = 0; kx < 3; ++kx) {
#pragma unroll
                for (int ks = 0; ks < 2; ++ks) {
                    uint32_t a_r[2][4];
#pragma unroll
                    for (int mf = 0; mf < 2; ++mf) {
                        int px = (wm + ky) * 34 + mf * 16 + apx + kx;
                        ldm_x4(a_r[mf], AsU + (uint32_t)(px * APITCH + ks * 32 + acol));
                    }
                    uint32_t b_r[4][4];
#pragma unroll
                    for (int nh = 0; nh < 4; ++nh) {
                        int row = nh * 16 + brow_in;
                        ldm_x4(b_r[nh], Bbr + (uint32_t)(((ky * 3 + kx) * 64 + row) * BPITCH + ks * 32 + bcol));
                    }
#pragma unroll
                    for (int mf = 0; mf < 2; ++mf)
#pragma unroll
                        for (int nf = 0; nf < 8; ++nf)
                            mma16816(acc[mf][nf], a_r[mf], &b_r[nf >> 1][(nf & 1) * 2]);
                }
            }
        }

        // --- epilogue: two branch passes through Os (aliases A)
        const int prow  = lane >> 2;
        const int cbase = 2 * (lane & 3);
#pragma unroll
        for (int p = 0; p < 2; ++p) {
            __syncthreads();   // p=0: all ldm done (A dead); p=1: prior copy done
            if (wn == p) {
#pragma unroll
                for (int mf = 0; mf < 2; ++mf) {
#pragma unroll
                    for (int nf = 0; nf < 8; ++nf) {
                        int co = cbase + nf * 8;
                        float b0 = bias_s[p * 64 + co], b1 = bias_s[p * 64 + co + 1];
                        float f0 = fmaxf(acc[mf][nf][0] + b0, 0.f);
                        float f1 = fmaxf(acc[mf][nf][1] + b1, 0.f);
                        float f2 = fmaxf(acc[mf][nf][2] + b0, 0.f);
                        float f3 = fmaxf(acc[mf][nf][3] + b1, 0.f);
                        __half2 v0 = __float22half2_rn(make_float2(f0, f1));
                        __half2 v1 = __float22half2_rn(make_float2(f2, f3));
                        int opx0 = wm * 32 + mf * 16 + prow;
                        *(uint32_t*)(Os + opx0 * OPITCH + co * 2)       = *(uint32_t*)&v0;
                        *(uint32_t*)(Os + (opx0 + 8) * OPITCH + co * 2) = *(uint32_t*)&v1;
                    }
                }
            }
            __syncthreads();
            __half* outh = p ? out1 : out0;
            for (int i = tid; i < 128 * 8; i += 256) {
                int c   = i & 7;
                int opx = i >> 3;
                int r   = opx >> 5, lpx = opx & 31;
                uint4 v = *(const uint4*)(Os + opx * OPITCH + c * 16);
                size_t g = (((size_t)batch * HW + (y0 + r)) * HW + (x0 + lpx)) * 64 + c * 8;
                *(uint4*)&outh[g] = v;
            }
        }
    }
}

// ---------------------------------------------------------------------------
// conv2: 64 -> 64 (unchanged committed winner).
// ---------------------------------------------------------------------------
__global__ void __launch_bounds__(256, 2)
conv2_hmma(const __half* __restrict__ in0, const __half* __restrict__ in1,
           const __half* __restrict__ wp0, const __half* __restrict__ wp1,
           const float* __restrict__ bias0, const float* __restrict__ bias1,
           __half* __restrict__ out0, __half* __restrict__ out1)
{
    constexpr int CIN    = 64;
    constexpr int APITCH = CIN * 2 + 16;     // 144
    constexpr int BPITCH = CIN * 2 + 16;
    constexpr int KSTEPS = 4;
    constexpr int NPX    = 10 * 34;
    constexpr int BSZ    = 3 * 64 * BPITCH;
    constexpr int OPITCH = 144;

    extern __shared__ char sm[];
    float* bias_s = (float*)sm;
    char*  As = sm + 256;
    char*  Bs = As + NPX * APITCH;
    char*  Os = sm + 256;                    // epilogue staging reuses As/Bs

    const int tid  = threadIdx.x;
    const int lane = tid & 31;
    const int wm   = tid >> 5;
    const int x0   = blockIdx.x * 32;
    const int y0   = blockIdx.y * 8;
    const int bz   = blockIdx.z;
    const int batch = bz & (BATCH - 1);
    const int br    = bz >> 2;

    const __half* in   = br ? in1 : in0;
    const __half* wp   = br ? wp1 : wp0;
    const float*  bias = br ? bias1 : bias0;
    __half*       outh = br ? out1 : out0;

    if (tid < 64) bias_s[tid] = bias[tid];

    float acc[2][8][4];
#pragma unroll
    for (int mf = 0; mf < 2; ++mf)
#pragma unroll
        for (int nf = 0; nf < 8; ++nf)
#pragma unroll
            for (int q = 0; q < 4; ++q) acc[mf][nf][q] = 0.f;

    const uint32_t AsU = smem_u32(As);
    const uint32_t BsU = smem_u32(Bs);

    {
        const __half* ib = in + (size_t)batch * HW * HW * CIN;
        constexpr int CH = CIN / 8;
        for (int i = tid; i < NPX * CH; i += 256) {
            int c   = i % CH;
            int px  = i / CH;
            int irow = px / 34, col = px % 34;
            int gy = y0 - 1 + irow;
            int gx = x0 - 1 + col;
            bool ok = (unsigned)gy < HW && (unsigned)gx < HW;
            int cgy = ok ? gy : 0, cgx = ok ? gx : 0;
            cp16(AsU + px * APITCH + c * 16,
                 ib + ((size_t)cgy * HW + cgx) * CIN + c * 8, ok ? 16 : 0);
        }
    }

    constexpr int CH = CIN / 8;
    auto stage_B3 = [&](int ky, uint32_t dstBase) {
        for (int i = tid; i < 3 * 64 * CH; i += 256) {
            int c   = i % CH;
            int row = (i / CH) & 63;
            int tap = i / (CH * 64);
            cp16(dstBase + (tap * 64 + row) * BPITCH + c * 16,
                 wp + ((size_t)(ky * 3 + tap) * 64 + row) * CIN + c * 8, 16);
        }
    };

    stage_B3(0, BsU);
    cp_commit();
    cp_wait_all();
    __syncthreads();

    const int brow_in = (lane & 7) + ((lane >> 4) & 1) * 8;
    const int bcol    = ((lane >> 3) & 1) * 16;
    const int acol    = (lane >> 4) * 16;
    const int apx     = (lane & 15);

    for (int ky = 0; ky < 3; ++ky) {
        if (ky < 2) {
            stage_B3(ky + 1, BsU + ((ky + 1) & 1) * BSZ);
            cp_commit();
        }
        const uint32_t Bbase = BsU + (ky & 1) * BSZ;

#pragma unroll
        for (int kx = 0; kx < 3; ++kx) {
#pragma unroll
            for (int ks = 0; ks < KSTEPS; ++ks) {
                uint32_t a_r[2][4];
#pragma unroll
                for (int mf = 0; mf < 2; ++mf) {
                    int px = (wm + ky) * 34 + mf * 16 + apx + kx;
                    ldm_x4(a_r[mf], AsU + (uint32_t)(px * APITCH + ks * 32 + acol));
                }
                uint32_t b_r[4][4];
#pragma unroll
                for (int nh = 0; nh < 4; ++nh) {
                    int row = nh * 16 + brow_in;
                    ldm_x4(b_r[nh], Bbase + (uint32_t)((kx * 64 + row) * BPITCH + ks * 32 + bcol));
                }
#pragma unroll
                for (int mf = 0; mf < 2; ++mf)
#pragma unroll
                    for (int nf = 0; nf < 8; ++nf)
                        mma16816(acc[mf][nf], a_r[mf], &b_r[nf >> 1][(nf & 1) * 2]);
            }
        }
        if (ky < 2) {
            cp_wait_all();
            __syncthreads();
        }
    }

    __syncthreads();
    {
        const int prow  = lane >> 2;
        const int cbase = 2 * (lane & 3);
#pragma unroll
        for (int mf = 0; mf < 2; ++mf) {
#pragma unroll
            for (int nf = 0; nf < 8; ++nf) {
                int co = cbase + nf * 8;
                float b0 = bias_s[co], b1 = bias_s[co + 1];
                float f0 = fmaxf(acc[mf][nf][0] + b0, 0.f);
                float f1 = fmaxf(acc[mf][nf][1] + b1, 0.f);
                float f2 = fmaxf(acc[mf][nf][2] + b0, 0.f);
                float f3 = fmaxf(acc[mf][nf][3] + b1, 0.f);
                __half2 v0 = __float22half2_rn(make_float2(f0, f1));
                __half2 v1 = __float22half2_rn(make_float2(f2, f3));
                int opx0 = wm * 32 + mf * 16 + prow;
                *(uint32_t*)(Os + opx0 * OPITCH + co * 2)       = *(uint32_t*)&v0;
                *(uint32_t*)(Os + (opx0 + 8) * OPITCH + co * 2) = *(uint32_t*)&v1;
            }
        }
    }
    __syncthreads();
    for (int i = tid; i < 256 * 8; i += 256) {
        int c   = i & 7;
        int opx = i >> 3;
        int wmw = opx >> 5, lpx = opx & 31;
        uint4 v = *(const uint4*)(Os + opx * OPITCH + c * 16);
        size_t g = (((size_t)batch * HW + (y0 + wmw)) * HW + (x0 + lpx)) * 64 + c * 8;
        *(uint4*)&outh[g] = v;
    }
}

// ---------------------------------------------------------------------------
// Head: GAP(f4) -> FC chain -> softmax -> pred_cls + argmax cls
// ---------------------------------------------------------------------------
__global__ void head_kernel(const float* __restrict__ f4,
                            const float* __restrict__ Wc1, const float* __restrict__ bc1,
                            const float* __restrict__ Wc2, const float* __restrict__ bc2,
                            const float* __restrict__ Wc3, const float* __restrict__ bc3,
                            float* __restrict__ out_pred)
{
    __shared__ float gap[256];
    __shared__ float z1[128];
    __shared__ float z2[128];
    __shared__ float logits[3];

    const int b = blockIdx.x;
    const int tid = threadIdx.x;

    const float* p = f4 + (size_t)b * 1024 * 256 + tid;
    float s0 = 0.f, s1 = 0.f, s2 = 0.f, s3 = 0.f;
    for (int i = 0; i < 1024; i += 4) {
        s0 += p[(i + 0) * 256];
        s1 += p[(i + 1) * 256];
        s2 += p[(i + 2) * 256];
        s3 += p[(i + 3) * 256];
    }
    gap[tid] = (s0 + s1 + s2 + s3) * (1.0f / 1024.0f);
    __syncthreads();

    if (tid < 128) {
        float a = bc1[tid];
#pragma unroll 8
        for (int k = 0; k < 256; ++k) a = fmaf(gap[k], Wc1[k * 128 + tid], a);
        z1[tid] = fmaxf(a, 0.f);
    }
    __syncthreads();

    if (tid < 128) {
        float a = bc2[tid];
#pragma unroll 8
        for (int k = 0; k < 128; ++k) a = fmaf(z1[k], Wc2[k * 128 + tid], a);
        z2[tid] = fmaxf(a, 0.f);
    }
    __syncthreads();

    if (tid < 3) {
        float a = bc3[tid];
        for (int k = 0; k < 128; ++k) a = fmaf(z2[k], Wc3[k * 3 + tid], a);
        logits[tid] = a;
    }
    __syncthreads();

    if (tid == 0) {
        float l0 = logits[0], l1 = logits[1], l2 = logits[2];
        float m = fmaxf(l0, fmaxf(l1, l2));
        float e0 = expf(l0 - m), e1 = expf(l1 - m), e2 = expf(l2 - m);
        float inv = 1.f / (e0 + e1 + e2);
        out_pred[b * 3 + 0] = e0 * inv;
        out_pred[b * 3 + 1] = e1 * inv;
        out_pred[b * 3 + 2] = e2 * inv;
        int c = 0; float best = l0;
        if (l1 > best) { best = l1; c = 1; }
        if (l2 > best) { best = l2; c = 2; }
        g_cls[b] = c;
    }
}

// ---------------------------------------------------------------------------
// Final gather-conv as two thin HMMA GEMMs (unchanged committed winner).
// ---------------------------------------------------------------------------
__global__ void __launch_bounds__(256, 2)
conv3_select(const __half* __restrict__ h2o, const __half* __restrict__ h2w,
             const float* __restrict__ Wo3, const float* __restrict__ bo3,
             const float* __restrict__ Ww3, const float* __restrict__ bw3,
             float* __restrict__ out)
{
    constexpr int PITCH = 64 * 2 + 16;      // 144 B per pixel row
    constexpr int BP    = 576 * 2 + 16;     // 1168 B per n-row
    extern __shared__ char sm3[];
    char* ho = sm3;                         // 324 * 144
    char* hw = ho + 324 * PITCH;            // 324 * 144
    char* Bo = hw + 324 * PITCH;            // 8 * 1168
    char* Bw = Bo + 8 * BP;                 // 8 * 1168

    const int b   = blockIdx.z;
    const int y0  = blockIdx.y * 16;
    const int x0  = blockIdx.x * 16;
    const int tid = threadIdx.x;
    const int lane = tid & 31;
    const int wid  = tid >> 5;
    const int cls  = g_cls[b];

    const uint32_t hoU = smem_u32(ho);
    const uint32_t hwU = smem_u32(hw);
    const uint32_t BoU = smem_u32(Bo);
    const uint32_t BwU = smem_u32(Bw);

    const __half* po = h2o + (size_t)b * HW * HW * 64;
    const __half* pw = h2w + (size_t)b * HW * HW * 64;
    for (int i = tid; i < 324 * 8; i += 256) {
        int c  = i & 7;
        int px = i >> 3;
        int r = px / 18, cc = px % 18;
        int gy = y0 + r - 1, gx = x0 + cc - 1;
        bool ok = (unsigned)gy < HW && (unsigned)gx < HW;
        int cgy = ok ? gy : 0, cgx = ok ? gx : 0;
        size_t g = ((size_t)cgy * HW + cgx) * 64 + c * 8;
        cp16(hoU + px * PITCH + c * 16, po + g, ok ? 16 : 0);
        cp16(hwU + px * PITCH + c * 16, pw + g, ok ? 16 : 0);
    }
    cp_commit();

    for (int i = tid; i < (6 + 7) * (BP / 4); i += 256) {
        int j = i / (BP / 4);
        int w4 = i % (BP / 4);
        char* base = (j < 6) ? (Bo + (2 + j) * BP) : (Bw + (1 + j - 6) * BP);
        ((uint32_t*)base)[w4] = 0;
    }
    for (int i = tid; i < 576; i += 256) {
        *(__half*)(Bo + 0 * BP + i * 2) = __float2half_rn(Wo3[i * 6 + 2 * cls]);
        *(__half*)(Bo + 1 * BP + i * 2) = __float2half_rn(Wo3[i * 6 + 2 * cls + 1]);
        *(__half*)(Bw + 0 * BP + i * 2) = __float2half_rn(Ww3[i * 3 + cls]);
    }
    cp_wait_all();
    __syncthreads();

    float acc_o[2][4], acc_w[2][4];
#pragma unroll
    for (int mf = 0; mf < 2; ++mf)
#pragma unroll
        for (int q = 0; q < 4; ++q) { acc_o[mf][q] = 0.f; acc_w[mf][q] = 0.f; }

    const int mt0  = wid * 2;
    const int apx  = lane & 15;
    const int acol = (lane >> 4) * 16;
    const uint32_t boff = (uint32_t)((lane & 7) * BP + (lane >> 3) * 16);

    for (int tap = 0; tap < 9; ++tap) {
        const int ky = tap / 3, kx = tap % 3;
#pragma unroll
        for (int kp = 0; kp < 2; ++kp) {
            const uint32_t kbyte = (uint32_t)((tap * 64 + kp * 32) * 2);
            uint32_t b_o[4], b_w[4];
            ldm_x4(b_o, BoU + boff + kbyte);
            ldm_x4(b_w, BwU + boff + kbyte);
#pragma unroll
            for (int ks2 = 0; ks2 < 2; ++ks2) {
                uint32_t a_o[2][4], a_w[2][4];
#pragma unroll
                for (int mf = 0; mf < 2; ++mf) {
                    int px = (mt0 + mf + ky) * 18 + apx + kx;
                    uint32_t off = (uint32_t)(px * PITCH + (kp * 32 + ks2 * 16) * 2 + acol);
                    ldm_x4(a_o[mf], hoU + off);
                    ldm_x4(a_w[mf], hwU + off);
                }
#pragma unroll
                for (int mf = 0; mf < 2; ++mf) {
                    mma16816(acc_o[mf], a_o[mf], &b_o[ks2 * 2]);
                    mma16816(acc_w[mf], a_w[mf], &b_w[ks2 * 2]);
                }
            }
        }
    }

    if ((lane & 3) == 0) {
        const float bo0 = bo3[2 * cls], bo1 = bo3[2 * cls + 1], bwv = bw3[cls];
        const int pr = lane >> 2;
#pragma unroll
        for (int mf = 0; mf < 2; ++mf) {
            int gy = y0 + mt0 + mf;
#pragma unroll
            for (int h = 0; h < 2; ++h) {
                int gx = x0 + pr + h * 8;
                float o0 = acc_o[mf][h * 2 + 0] + bo0;
                float o1 = acc_o[mf][h * 2 + 1] + bo1;
                float wv = acc_w[mf][h * 2 + 0] + bwv;
                size_t pix = ((size_t)b * HW + gy) * HW + gx;
                *(float2*)&out[pix * 2] = make_float2(o0, o1);
                out[(size_t)BATCH * HW * HW * 2 + pix] = wv;
            }
        }
    }
}

// ---------------------------------------------------------------------------
extern "C" void kernel_launch(void* const* d_in, const int* in_sizes, int n_in,
                              void* d_out, int out_size)
{
    (void)in_sizes; (void)n_in; (void)out_size;
    const float* x0  = (const float*)d_in[0];
    const float* f4  = (const float*)d_in[1];
    const float* Wo1 = (const float*)d_in[2];
    const float* bo1 = (const float*)d_in[3];
    const float* Wo2 = (const float*)d_in[4];
    const float* bo2 = (const float*)d_in[5];
    const float* Wo3 = (const float*)d_in[6];
    const float* bo3 = (const float*)d_in[7];
    const float* Ww1 = (const float*)d_in[8];
    const float* bw1 = (const float*)d_in[9];
    const float* Ww2 = (const float*)d_in[10];
    const float* bw2 = (const float*)d_in[11];
    const float* Ww3 = (const float*)d_in[12];
    const float* bw3 = (const float*)d_in[13];
    const float* Wc1 = (const float*)d_in[14];
    const float* bc1 = (const float*)d_in[15];
    const float* Wc2 = (const float*)d_in[16];
    const float* bc2 = (const float*)d_in[17];
    const float* Wc3 = (const float*)d_in[18];
    const float* bc3 = (const float*)d_in[19];
    float* out = (float*)d_out;

    void *pH1o, *pH1w, *pH2o, *pH2w, *pW1o, *pW1w, *pW2o, *pW2w;
    cudaGetSymbolAddress(&pH1o, g_h1o);
    cudaGetSymbolAddress(&pH1w, g_h1w);
    cudaGetSymbolAddress(&pH2o, g_h2o);
    cudaGetSymbolAddress(&pH2w, g_h2w);
    cudaGetSymbolAddress(&pW1o, g_wp1o);
    cudaGetSymbolAddress(&pW1w, g_wp1w);
    cudaGetSymbolAddress(&pW2o, g_wp2o);
    cudaGetSymbolAddress(&pW2w, g_wp2w);

    const size_t smem1 = 512 + 18432 + (size_t)2 * 9 * 64 * 80;               // 111.0 KB
    const size_t smem2 = 256 + (size_t)340 * 144 + (size_t)2 * 3 * 64 * 144;  // 102.1 KB
    const size_t smem3 = (size_t)2 * 324 * 144 + (size_t)16 * 1168;           // 109.4 KB

    cudaFuncSetAttribute((const void*)conv1_fused,
                         cudaFuncAttributeMaxDynamicSharedMemorySize, (int)smem1);
    cudaFuncSetAttribute((const void*)conv2_hmma,
                         cudaFuncAttributeMaxDynamicSharedMemorySize, (int)smem2);
    cudaFuncSetAttribute((const void*)conv3_select,
                         cudaFuncAttributeMaxDynamicSharedMemorySize, (int)smem3);

    float* pred = out + (size_t)BATCH * HW * HW * 3;

    head_kernel<<<BATCH, 256>>>(f4, Wc1, bc1, Wc2, bc2, Wc3, bc3, pred);
    prep_all<<<dim3(36, 4), 256>>>(Wo1, Ww1, Wo2, Ww2,
                                   (__half*)pW1o, (__half*)pW1w,
                                   (__half*)pW2o, (__half*)pW2w);

    dim3 g1(HW / 32, HW / 32, BATCH);   // 16 x 16 x 4 = 1024 blocks, 8 y-tiles each
    conv1_fused<<<g1, 256, smem1>>>(
        x0, (__half*)pW1o, (__half*)pW1w, bo1, bw1,
        (__half*)pH1o, (__half*)pH1w);

    dim3 g2(HW / 32, HW / 8, 2 * BATCH);
    conv2_hmma<<<g2, 256, smem2>>>(
        (__half*)pH1o, (__half*)pH1w, (__half*)pW2o, (__half*)pW2w, bo2, bw2,
        (__half*)pH2o, (__half*)pH2w);

    dim3 g3(HW / 16, HW / 16, BATCH);
    conv3_select<<<g3, 256, smem3>>>((__half*)pH2o, (__half*)pH2w,
                                     Wo3, bo3, Ww3, bw3, out);
}